// round 9
// baseline (speedup 1.0000x reference)
#include <cuda_runtime.h>

#define RADIUS 5
#define TX     32
#define TY     4                     /* threads in y; each owns 4 pixel rows */
#define NC     4                     /* centers per thread */
#define PY     (NC*TY)               /* 16 pixel rows per block */
#define SW     (TX + 2*RADIUS)       /* 42 */
#define SH     (PY + RADIUS)         /* 21: bottom halo only (symmetric pairs) */
#define NB     8
#define NK     4
#define IMH    224
#define IMW    224
#define NBLK   ((IMW/TX) * (IMH/PY) * NB)   /* 7*14*8 = 784 = 5.3 blocks/SM */

// Weight: exp2(-(s*(xr-xc))^2 + C_DST*(dy^2+dx^2)), s = 255*sqrt(log2e/100).
#define SCALE  (30.634556f)                  /* 255 * sqrt(log2(e)/100) */
#define C_DST  (-0.09016844005555897f)       /* -log2e / 16 */

__device__ __forceinline__ float ex2(float x) {
    float y;
    asm("ex2.approx.ftz.f32 %0, %1;" : "=f"(y) : "f"(x));
    return y;
}

// Packed fp32x2 helpers (FFMA2 is only reachable via explicit PTX).
__device__ __forceinline__ unsigned long long pack2(float lo, float hi) {
    unsigned long long v;
    asm("mov.b64 %0, {%1, %2};" : "=l"(v) : "f"(lo), "f"(hi));
    return v;
}
__device__ __forceinline__ void unpack2(unsigned long long v, float& lo, float& hi) {
    asm("mov.b64 {%0, %1}, %2;" : "=f"(lo), "=f"(hi) : "l"(v));
}
__device__ __forceinline__ void ffma2(unsigned long long& acc,
                                      unsigned long long a, unsigned long long b) {
    asm("fma.rn.f32x2 %0, %1, %2, %0;" : "+l"(acc) : "l"(a), "l"(b));
}

// [b][k][{A,B}] accumulators (double) + completion counter. Zero at load;
// the last block resets them, so graph replays are deterministic.
__device__ double       g_acc[NB * NK * 2];
__device__ unsigned int g_count;

struct Ctr {
    float c;                      // pre-scaled center intensity
    float4 p;                     // center class probs
    float S1;                     // sum of weights (positive offsets)
    unsigned long long s01, s23;  // packed (s0,s1), (s2,s3) accumulators
    __device__ __forceinline__ void init(float cc, float4 pp) {
        c = cc; p = pp; S1 = 0.f; s01 = 0ull; s23 = 0ull;
    }
    __device__ __forceinline__ void ev(float r, unsigned long long q01,
                                       unsigned long long q23, float dconst) {
        const float d = r - c;
        const float w = ex2(fmaf(-d, d, dconst));
        S1 += w;
        const unsigned long long w2 = pack2(w, w);
        ffma2(s01, w2, q01);
        ffma2(s23, w2, q23);
    }
};

__global__ __launch_bounds__(TX * TY, 6) void k_main(const float* __restrict__ images,
                                                     const float* __restrict__ labels,
                                                     float* __restrict__ out) {
    __shared__ float  s_img[SH * SW];
    __shared__ float4 s_lab[SH * SW];
    __shared__ float  s_red[TY][8];
    __shared__ bool   s_last;

    const int tx  = threadIdx.x;
    const int ty  = threadIdx.y;
    const int tid = ty * TX + tx;
    const int b   = blockIdx.z;
    const int y0  = blockIdx.y * PY;
    const int x0  = blockIdx.x * TX;

    const float* imgb = images + (size_t)b * IMH * IMW;
    const float* labb = labels + (size_t)b * NK * IMH * IMW;

    // Halo: y in [y0, y0+PY+RADIUS), x in [x0-RADIUS, x0+TX+RADIUS).
    // Out-of-image: sentinel 1e10 -> weight underflows to exactly 0
    // (implements the boundary mask symmetrically); labels 0.
    for (int i = tid; i < SH * SW; i += TX * TY) {
        int sy = i / SW;
        int sx = i - sy * SW;
        int gy = y0 + sy;
        int gx = x0 + sx - RADIUS;
        bool in = ((unsigned)gy < IMH) && ((unsigned)gx < IMW);
        int g = gy * IMW + gx;
        s_img[i] = in ? imgb[g] * SCALE : 1e10f;
        float4 L = make_float4(0.f, 0.f, 0.f, 0.f);
        if (in) {
            L.x = labb[0 * IMH * IMW + g];
            L.y = labb[1 * IMH * IMW + g];
            L.z = labb[2 * IMH * IMW + g];
            L.w = labb[3 * IMH * IMW + g];
        }
        s_lab[i] = L;
    }
    __syncthreads();

    // 4 vertically adjacent centers per thread: rows NC*ty + 0..3.
    Ctr A[NC];
    const int ci0 = (NC * ty) * SW + tx + RADIUS;
    #pragma unroll
    for (int k = 0; k < NC; k++)
        A[k].init(s_img[ci0 + k * SW], s_lab[ci0 + k * SW]);

    // Positive half-stencil over rows o = 0..NC-1+RADIUS; each shared-memory
    // point (o, dx) feeds every center k with 0 <= dy = o-k <= RADIUS
    // (dy == 0 restricted to dx >= 1). All loop bounds compile-time.
    #pragma unroll
    for (int o = 0; o <= NC - 1 + RADIUS; o++) {
        const int base = ci0 + o * SW;
        #pragma unroll
        for (int dx = -RADIUS; dx <= RADIUS; dx++) {
            if (o == 0 && dx < 1) continue;      // no consumer for this point
            const int    j = base + dx;
            const float  r = s_img[j];
            const float4 q = s_lab[j];
            const unsigned long long q01 = pack2(q.x, q.y);
            const unsigned long long q23 = pack2(q.z, q.w);
            #pragma unroll
            for (int k = 0; k < NC; k++) {
                const int dy = o - k;
                if (dy < 0 || dy > RADIUS) continue;
                if (dy == 0 && dx < 1) continue;
                A[k].ev(r, q01, q23, C_DST * (float)(dy * dy + dx * dx));
            }
        }
    }

    // Symmetric closure (w_ii = 1), summed over the NC centers:
    //   A_k += p_k*(p_k + 2*S2_k);   B_k += p_k*(1+S1) + S2_k
    float v[8] = {0.f, 0.f, 0.f, 0.f, 0.f, 0.f, 0.f, 0.f};
    #pragma unroll
    for (int k = 0; k < NC; k++) {
        float s0, s1, s2, s3;
        unpack2(A[k].s01, s0, s1);
        unpack2(A[k].s23, s2, s3);
        const float g1 = 1.f + A[k].S1;
        v[0] += A[k].p.x * fmaf(2.f, s0, A[k].p.x);
        v[1] += A[k].p.y * fmaf(2.f, s1, A[k].p.y);
        v[2] += A[k].p.z * fmaf(2.f, s2, A[k].p.z);
        v[3] += A[k].p.w * fmaf(2.f, s3, A[k].p.w);
        v[4] += fmaf(A[k].p.x, g1, s0);
        v[5] += fmaf(A[k].p.y, g1, s1);
        v[6] += fmaf(A[k].p.z, g1, s2);
        v[7] += fmaf(A[k].p.w, g1, s3);
    }

    #pragma unroll
    for (int jj = 0; jj < 8; jj++) {
        float s = v[jj];
        #pragma unroll
        for (int o = 16; o > 0; o >>= 1)
            s += __shfl_xor_sync(0xffffffffu, s, o);
        if (tx == 0) s_red[ty][jj] = s;
    }
    __syncthreads();

    if (tid < 8) {
        float s = 0.f;
        #pragma unroll
        for (int w = 0; w < TY; w++) s += s_red[w][tid];
        const int k     = tid & 3;
        const int which = tid >> 2;   // 0 = A (num), 1 = B (den)
        atomicAdd(&g_acc[(b * NK + k) * 2 + which], (double)s);
    }

    // ---- last-block finalize ----
    __threadfence();
    if (tid == 0)
        s_last = (atomicAdd(&g_count, 1u) == NBLK - 1u);
    __syncthreads();

    if (s_last) {
        __threadfence();
        if (tid < NB * NK) {           // 32 parallel double divides
            double Av = g_acc[tid * 2 + 0];
            double Bv = g_acc[tid * 2 + 1];
            double r  = fabs(Av / Bv);
            #pragma unroll
            for (int o = 16; o > 0; o >>= 1)
                r += __shfl_xor_sync(0xffffffffu, r, o);
            if (tid == 0)
                out[0] = (float)((double)NK - r / (double)NB);
        }
        __syncthreads();
        if (tid < NB * NK * 2) g_acc[tid] = 0.0;
        if (tid == 0) g_count = 0u;
    }
}

extern "C" void kernel_launch(void* const* d_in, const int* in_sizes, int n_in,
                              void* d_out, int out_size) {
    const float* images = (const float*)d_in[0];
    const float* labels = (const float*)d_in[1];
    if (n_in >= 2 && in_sizes[0] > in_sizes[1]) {   // robust to input ordering
        images = (const float*)d_in[1];
        labels = (const float*)d_in[0];
    }

    dim3 grid(IMW / TX, IMH / PY, NB);
    dim3 blk(TX, TY);
    k_main<<<grid, blk>>>(images, labels, (float*)d_out);
}

// round 10
// speedup vs baseline: 1.0740x; 1.0740x over previous
#include <cuda_runtime.h>

#define RADIUS 5
#define TX     32
#define TY     4                     /* 128-thread blocks */
#define NC     4                     /* centers per thread */
#define PY     (NC*TY)               /* 16 pixel rows per block */
#define SW     (TX + 2*RADIUS)       /* 42 */
#define SH     (PY + RADIUS)         /* 21: bottom halo only (symmetric pairs) */
#define NB     8
#define NK     4
#define IMH    224
#define IMW    224
#define NBLK   ((IMW/TX) * (IMH/PY) * NB)   /* 784 blocks */

// Weight: exp2(-(s*(xr-xc))^2 + C_DST*(dy^2+dx^2)), s = 255*sqrt(log2e/100).
#define SCALE  (30.634556f)                  /* 255 * sqrt(log2(e)/100) */
#define C_DST  (-0.09016844005555897f)       /* -log2e / 16 */

__device__ __forceinline__ float ex2(float x) {
    float y;
    asm("ex2.approx.ftz.f32 %0, %1;" : "=f"(y) : "f"(x));
    return y;
}

// Packed fp32x2 helpers (FFMA2 is only reachable via explicit PTX).
__device__ __forceinline__ unsigned long long pack2(float lo, float hi) {
    unsigned long long v;
    asm("mov.b64 %0, {%1, %2};" : "=l"(v) : "f"(lo), "f"(hi));
    return v;
}
__device__ __forceinline__ void unpack2(unsigned long long v, float& lo, float& hi) {
    asm("mov.b64 {%0, %1}, %2;" : "=f"(lo), "=f"(hi) : "l"(v));
}
__device__ __forceinline__ void ffma2(unsigned long long& acc,
                                      unsigned long long a, unsigned long long b) {
    asm("fma.rn.f32x2 %0, %1, %2, %0;" : "+l"(acc) : "l"(a), "l"(b));
}

// [b][k][{A,B}] accumulators (double) + completion counter. Zero at load;
// the last block resets them, so graph replays are deterministic.
__device__ double       g_acc[NB * NK * 2];
__device__ unsigned int g_count;

// Accumulator-only state: center probs p stay in smem until the closure,
// keeping live registers per center at 6 (c, S1, s01, s23) instead of 10.
struct Ctr {
    float c;                      // pre-scaled center intensity
    float S1;                     // sum of weights (positive offsets)
    unsigned long long s01, s23;  // packed (s0,s1), (s2,s3)
    __device__ __forceinline__ void init(float cc) {
        c = cc; S1 = 0.f; s01 = 0ull; s23 = 0ull;
    }
    __device__ __forceinline__ void ev(float r, unsigned long long q01,
                                       unsigned long long q23, float dconst) {
        const float d = r - c;
        const float w = ex2(fmaf(-d, d, dconst));
        S1 += w;
        const unsigned long long w2 = pack2(w, w);
        ffma2(s01, w2, q01);
        ffma2(s23, w2, q23);
    }
};

__global__ __launch_bounds__(TX * TY, 8) void k_main(const float* __restrict__ images,
                                                     const float* __restrict__ labels,
                                                     float* __restrict__ out) {
    __shared__ float  s_img[SH * SW];
    __shared__ float4 s_lab[SH * SW];
    __shared__ float  s_red[TY][8];
    __shared__ bool   s_last;

    const int tx  = threadIdx.x;
    const int ty  = threadIdx.y;
    const int tid = ty * TX + tx;
    const int b   = blockIdx.z;
    const int y0  = blockIdx.y * PY;
    const int x0  = blockIdx.x * TX;

    const float* imgb = images + (size_t)b * IMH * IMW;
    const float* labb = labels + (size_t)b * NK * IMH * IMW;

    // Halo: y in [y0, y0+PY+RADIUS), x in [x0-RADIUS, x0+TX+RADIUS).
    // Out-of-image: sentinel 1e10 -> weight underflows to exactly 0
    // (implements the boundary mask symmetrically); labels 0.
    for (int i = tid; i < SH * SW; i += TX * TY) {
        int sy = i / SW;
        int sx = i - sy * SW;
        int gy = y0 + sy;
        int gx = x0 + sx - RADIUS;
        bool in = ((unsigned)gy < IMH) && ((unsigned)gx < IMW);
        int g = gy * IMW + gx;
        s_img[i] = in ? imgb[g] * SCALE : 1e10f;
        float4 L = make_float4(0.f, 0.f, 0.f, 0.f);
        if (in) {
            L.x = labb[0 * IMH * IMW + g];
            L.y = labb[1 * IMH * IMW + g];
            L.z = labb[2 * IMH * IMW + g];
            L.w = labb[3 * IMH * IMW + g];
        }
        s_lab[i] = L;
    }
    __syncthreads();

    // 4 vertically adjacent centers per thread: rows NC*ty + 0..3.
    Ctr A[NC];
    const int ci0 = (NC * ty) * SW + tx + RADIUS;
    #pragma unroll
    for (int k = 0; k < NC; k++)
        A[k].init(s_img[ci0 + k * SW]);

    // Positive half-stencil over rows o = 0..NC-1+RADIUS; each shared-memory
    // point (o, dx) feeds every center k with 0 <= dy = o-k <= RADIUS
    // (dy == 0 restricted to dx >= 1). All loop bounds compile-time.
    #pragma unroll
    for (int o = 0; o <= NC - 1 + RADIUS; o++) {
        const int base = ci0 + o * SW;
        #pragma unroll
        for (int dx = -RADIUS; dx <= RADIUS; dx++) {
            if (o == 0 && dx < 1) continue;      // no consumer for this point
            const int    j = base + dx;
            const float  r = s_img[j];
            const float4 q = s_lab[j];
            const unsigned long long q01 = pack2(q.x, q.y);
            const unsigned long long q23 = pack2(q.z, q.w);
            #pragma unroll
            for (int k = 0; k < NC; k++) {
                const int dy = o - k;
                if (dy < 0 || dy > RADIUS) continue;
                if (dy == 0 && dx < 1) continue;
                A[k].ev(r, q01, q23, C_DST * (float)(dy * dy + dx * dx));
            }
        }
    }

    // Symmetric closure (w_ii = 1), summed over the NC centers:
    //   A_k += p_k*(p_k + 2*S2_k);   B_k += p_k*(1+S1) + S2_k
    // Center probs p re-read from smem here (not held across the stencil).
    float v[8] = {0.f, 0.f, 0.f, 0.f, 0.f, 0.f, 0.f, 0.f};
    #pragma unroll
    for (int k = 0; k < NC; k++) {
        const float4 p = s_lab[ci0 + k * SW];
        float s0, s1, s2, s3;
        unpack2(A[k].s01, s0, s1);
        unpack2(A[k].s23, s2, s3);
        const float g1 = 1.f + A[k].S1;
        v[0] += p.x * fmaf(2.f, s0, p.x);
        v[1] += p.y * fmaf(2.f, s1, p.y);
        v[2] += p.z * fmaf(2.f, s2, p.z);
        v[3] += p.w * fmaf(2.f, s3, p.w);
        v[4] += fmaf(p.x, g1, s0);
        v[5] += fmaf(p.y, g1, s1);
        v[6] += fmaf(p.z, g1, s2);
        v[7] += fmaf(p.w, g1, s3);
    }

    #pragma unroll
    for (int jj = 0; jj < 8; jj++) {
        float s = v[jj];
        #pragma unroll
        for (int o = 16; o > 0; o >>= 1)
            s += __shfl_xor_sync(0xffffffffu, s, o);
        if (tx == 0) s_red[ty][jj] = s;
    }
    __syncthreads();

    if (tid < 8) {
        float s = 0.f;
        #pragma unroll
        for (int w = 0; w < TY; w++) s += s_red[w][tid];
        const int k     = tid & 3;
        const int which = tid >> 2;   // 0 = A (num), 1 = B (den)
        atomicAdd(&g_acc[(b * NK + k) * 2 + which], (double)s);
    }

    // ---- last-block finalize ----
    __threadfence();
    if (tid == 0)
        s_last = (atomicAdd(&g_count, 1u) == NBLK - 1u);
    __syncthreads();

    if (s_last) {
        __threadfence();
        if (tid < NB * NK) {           // 32 parallel double divides
            double Av = g_acc[tid * 2 + 0];
            double Bv = g_acc[tid * 2 + 1];
            double r  = fabs(Av / Bv);
            #pragma unroll
            for (int o = 16; o > 0; o >>= 1)
                r += __shfl_xor_sync(0xffffffffu, r, o);
            if (tid == 0)
                out[0] = (float)((double)NK - r / (double)NB);
        }
        __syncthreads();
        if (tid < NB * NK * 2) g_acc[tid] = 0.0;
        if (tid == 0) g_count = 0u;
    }
}

extern "C" void kernel_launch(void* const* d_in, const int* in_sizes, int n_in,
                              void* d_out, int out_size) {
    const float* images = (const float*)d_in[0];
    const float* labels = (const float*)d_in[1];
    if (n_in >= 2 && in_sizes[0] > in_sizes[1]) {   // robust to input ordering
        images = (const float*)d_in[1];
        labels = (const float*)d_in[0];
    }

    dim3 grid(IMW / TX, IMH / PY, NB);
    dim3 blk(TX, TY);
    k_main<<<grid, blk>>>(images, labels, (float*)d_out);
}